// round 2
// baseline (speedup 1.0000x reference)
#include <cuda_runtime.h>
#include <cuda_bf16.h>

#define TPB    64
#define ROWF   60          // floats per row
#define STR    61          // smem row stride (odd -> bank-conflict-free)
#define NSTEP  10

__device__ float        g_partials[8192];
__device__ unsigned int g_count = 0;

// ---------------------------------------------------------------------------
// fast atan2: max abs err ~1e-5 rad. Rotation terms carry ~1e-5 of the loss
// mass (translation terms are ~1e6 vs rotation <= pi^2) -> far inside budget.
// ---------------------------------------------------------------------------
__device__ __forceinline__ float atan_core(float a) {   // a in [0,1]
    float s  = a * a;
    float r  = fmaf(0.024840285f, s, -0.11643287f);
    r = fmaf(r, s, 0.19354346f);
    r = fmaf(r, s, -0.33262348f);
    r = fmaf(r, s, 0.99997726f);
    return a * r;
}

__device__ __forceinline__ float fast_atan2f(float y, float x) {
    float ax = fabsf(x), ay = fabsf(y);
    float mx = fmaxf(ax, ay);
    float mn = fminf(ax, ay);
    float r  = atan_core(__fdividef(mn, mx));
    if (ay > ax)   r = 1.57079632679489662f - r;
    if (x < 0.0f)  r = 3.14159265358979323f - r;
    return copysignf(r, y);
}

// x >= 0 guaranteed (skips the pi - r quadrant flip)
__device__ __forceinline__ float fast_atan2_posx(float y, float x) {
    float ay = fabsf(y);
    float mx = fmaxf(x, ay);
    float mn = fminf(x, ay);
    float r  = atan_core(__fdividef(mn, mx));
    if (ay > x) r = 1.57079632679489662f - r;
    return copysignf(r, y);
}

// only the 7 rotation-matrix entries matrix_to_euler ever reads
struct M7 { float m0, m3, m4, m5, m6, m7, m8; };

__device__ __forceinline__ M7 euler_to_mat7(float x, float y, float z) {
    float cx, sx, cy, sy, cz, sz;
    __sincosf(x, &sx, &cx);
    __sincosf(y, &sy, &cy);
    __sincosf(z, &sz, &cz);
    M7 R;
    R.m0 = cz * cy;
    R.m3 = sz * cy;
    R.m4 = sz * sy * sx + cz * cx;
    R.m5 = sz * sy * cx - cz * sx;
    R.m6 = -sy;
    R.m7 = cy * sx;
    R.m8 = cy * cx;
    return R;
}

// rot euler of M = R1 .* pp (elementwise); warp-voted singular slow path
__device__ __forceinline__ void rot_euler(const M7& R1, const M7& pp,
                                          float& e0, float& e1, float& e2) {
    float M00 = R1.m0 * pp.m0;
    float M10 = R1.m3 * pp.m3;
    float M20 = R1.m6 * pp.m6;
    float M21 = R1.m7 * pp.m7;
    float M22 = R1.m8 * pp.m8;
    float s   = fmaf(M00, M00, M10 * M10);
    float sy  = sqrtf(s);
    bool sing = sy < 1e-6f;
    if (__builtin_expect(__any_sync(0xffffffffu, sing), 0)) {
        float M11 = R1.m4 * pp.m4;
        float M12 = R1.m5 * pp.m5;
        e0 = sing ? fast_atan2f(-M12, M11) : fast_atan2f(M21, M22);
        e2 = sing ? 0.0f                   : fast_atan2f(M10, M00);
    } else {
        e0 = fast_atan2f(M21, M22);
        e2 = fast_atan2f(M10, M00);
    }
    e1 = fast_atan2_posx(-M20, sy);
}

__global__ void __launch_bounds__(TPB)
cycle_loss_kernel(const float* __restrict__ pred, const float* __restrict__ gt,
                  float* __restrict__ out, double scale)
{
    __shared__ float sp[TPB * STR];
    __shared__ float sg[TPB * STR];
    const int tid = threadIdx.x;

    // ---- coalesced float4 stage into smem (odd stride 61) ----
    {
        long base = (long)blockIdx.x * TPB * ROWF;
        const float4* p4 = (const float4*)(pred + base);
        const float4* g4 = (const float4*)(gt + base);
        #pragma unroll
        for (int j = tid; j < TPB * (ROWF / 4); j += TPB) {
            int r = j / 15;
            int c = (j % 15) * 4;
            float4 v = p4[j];
            float* d = &sp[r * STR + c];
            d[0] = v.x; d[1] = v.y; d[2] = v.z; d[3] = v.w;
            float4 w = g4[j];
            float* d2 = &sg[r * STR + c];
            d2[0] = w.x; d2[1] = w.y; d2[2] = w.z; d2[3] = w.w;
        }
    }
    __syncthreads();

    const float* P = &sp[tid * STR];
    const float* G = &sg[tid * STR];

    float acc = 0.0f;

    // ---------------- translation part ----------------
    {
        float vp0 = P[0], vp1 = P[1], vp2 = P[2];
        float vg0 = G[0], vg1 = G[1], vg2 = G[2];
        float d0 = vp0 - vg0, d1 = vp1 - vg1, d2 = vp2 - vg2;
        acc += d0 * d0 + d1 * d1 + d2 * d2;
        float cp0 = 0.f, cp1 = 0.f, cp2 = 0.f;
        float cg0 = 0.f, cg1 = 0.f, cg2 = 0.f;
        #pragma unroll
        for (int i = 1; i < NSTEP; i++) {
            vp0 = 2.0f * vp0 + cp0;
            vp1 = 2.0f * vp1 + cp1;
            vp2 = 2.0f * vp2 + cp2;
            vg0 = 2.0f * vg0 + cg0;
            vg1 = 2.0f * vg1 + cg1;
            vg2 = 2.0f * vg2 + cg2;
            d0 = vp0 - vg0; d1 = vp1 - vg1; d2 = vp2 - vg2;
            acc += d0 * d0 + d1 * d1 + d2 * d2;
            const float* tp = &P[i * 6];
            const float* tg = &G[i * 6];
            cp0 += tp[0]; cp1 += tp[1]; cp2 += tp[2];
            cg0 += tg[0]; cg1 += tg[1]; cg2 += tg[2];
        }
    }

    // ---------------- rotation part ----------------
    {
        M7 R1p = euler_to_mat7(P[9], P[10], P[11]);
        M7 R1g = euler_to_mat7(G[9], G[10], G[11]);

        M7 pp = {1.f, 1.f, 1.f, 1.f, 1.f, 1.f, 1.f};
        M7 pg = {1.f, 1.f, 1.f, 1.f, 1.f, 1.f, 1.f};

        for (int i = 0; i < NSTEP; i++) {
            float ep0, ep1, ep2, eg0, eg1, eg2;
            rot_euler(R1p, pp, ep0, ep1, ep2);
            rot_euler(R1g, pg, eg0, eg1, eg2);
            float d0 = ep0 - eg0;
            float d1 = ep1 - eg1;
            float d2 = ep2 - eg2;
            acc += d0 * d0 + d1 * d1 + d2 * d2;

            if (i < NSTEP - 1) {            // last update unused
                M7 Rp = euler_to_mat7(P[i * 6 + 3], P[i * 6 + 4], P[i * 6 + 5]);
                M7 Rg = euler_to_mat7(G[i * 6 + 3], G[i * 6 + 4], G[i * 6 + 5]);
                pp.m0 *= Rp.m0; pp.m3 *= Rp.m3; pp.m4 *= Rp.m4; pp.m5 *= Rp.m5;
                pp.m6 *= Rp.m6; pp.m7 *= Rp.m7; pp.m8 *= Rp.m8;
                pg.m0 *= Rg.m0; pg.m3 *= Rg.m3; pg.m4 *= Rg.m4; pg.m5 *= Rg.m5;
                pg.m6 *= Rg.m6; pg.m7 *= Rg.m7; pg.m8 *= Rg.m8;
            }
        }
    }

    // ---------------- block reduction ----------------
    #pragma unroll
    for (int o = 16; o > 0; o >>= 1)
        acc += __shfl_down_sync(0xffffffffu, acc, o);

    __shared__ float wsum[TPB / 32];
    if ((tid & 31) == 0) wsum[tid >> 5] = acc;
    __syncthreads();

    __shared__ bool is_last;
    if (tid == 0) {
        float sblk = 0.0f;
        #pragma unroll
        for (int w = 0; w < TPB / 32; w++) sblk += wsum[w];
        g_partials[blockIdx.x] = sblk;
        __threadfence();
        unsigned int c = atomicAdd(&g_count, 1u);
        is_last = (c == gridDim.x - 1);
    }
    __syncthreads();

    // ---------------- last block: deterministic final reduce ----------------
    if (is_last) {
        double s = 0.0;
        for (int i = tid; i < (int)gridDim.x; i += TPB)
            s += (double)g_partials[i];
        #pragma unroll
        for (int o = 16; o > 0; o >>= 1)
            s += __shfl_down_sync(0xffffffffu, s, o);
        __shared__ double dsum[TPB / 32];
        if ((tid & 31) == 0) dsum[tid >> 5] = s;
        __syncthreads();
        if (tid == 0) {
            double t = 0.0;
            #pragma unroll
            for (int w = 0; w < TPB / 32; w++) t += dsum[w];
            out[0] = (float)(t * scale);
            g_count = 0;            // reset for next graph replay
        }
    }
}

extern "C" void kernel_launch(void* const* d_in, const int* in_sizes, int n_in,
                              void* d_out, int out_size)
{
    const float* pred = (const float*)d_in[0];
    const float* gt   = (const float*)d_in[1];
    int batch   = in_sizes[0] / ROWF;       // 262144
    int nblocks = batch / TPB;              // 4096

    // loss = mean over (B,10,2,3) / B  = sum / (60 * B * B)
    double scale = 1.0 / (60.0 * (double)batch * (double)batch);
    cycle_loss_kernel<<<nblocks, TPB>>>(pred, gt, (float*)d_out, scale);
}

// round 3
// speedup vs baseline: 1.3291x; 1.3291x over previous
#include <cuda_runtime.h>
#include <cuda_bf16.h>

#define TPB    128         // 64 rows/block, 2 signals per row (even=pred, odd=gt)
#define ROWS_B 64
#define ROWF   60          // floats per row
#define STR    61          // smem row stride (odd -> bank-conflict-free)
#define NSTEP  10

__device__ float        g_partials[8192];
__device__ unsigned int g_count = 0;

// ---------------------------------------------------------------------------
// fast atan2: max abs err ~1e-5 rad. Rotation terms carry ~1e-5 of the loss
// mass (translation terms are ~1e6 vs rotation <= pi^2) -> far inside budget.
// ---------------------------------------------------------------------------
__device__ __forceinline__ float atan_core(float a) {   // a in [0,1]
    float s  = a * a;
    float r  = fmaf(0.024840285f, s, -0.11643287f);
    r = fmaf(r, s, 0.19354346f);
    r = fmaf(r, s, -0.33262348f);
    r = fmaf(r, s, 0.99997726f);
    return a * r;
}

__device__ __forceinline__ float fast_atan2f(float y, float x) {
    float ax = fabsf(x), ay = fabsf(y);
    float mx = fmaxf(ax, ay);
    float mn = fminf(ax, ay);
    float r  = atan_core(__fdividef(mn, mx));
    if (ay > ax)   r = 1.57079632679489662f - r;
    if (x < 0.0f)  r = 3.14159265358979323f - r;
    return copysignf(r, y);
}

// x >= 0 guaranteed (skips the pi - r quadrant flip)
__device__ __forceinline__ float fast_atan2_posx(float y, float x) {
    float ay = fabsf(y);
    float mx = fmaxf(x, ay);
    float mn = fminf(x, ay);
    float r  = atan_core(__fdividef(mn, mx));
    if (ay > x) r = 1.57079632679489662f - r;
    return copysignf(r, y);
}

// only the 7 rotation-matrix entries matrix_to_euler ever reads
struct M7 { float m0, m3, m4, m5, m6, m7, m8; };

__device__ __forceinline__ M7 euler_to_mat7(float x, float y, float z) {
    float cx, sx, cy, sy, cz, sz;
    __sincosf(x, &sx, &cx);
    __sincosf(y, &sy, &cy);
    __sincosf(z, &sz, &cz);
    M7 R;
    R.m0 = cz * cy;
    R.m3 = sz * cy;
    R.m4 = sz * sy * sx + cz * cx;
    R.m5 = sz * sy * cx - cz * sx;
    R.m6 = -sy;
    R.m7 = cy * sx;
    R.m8 = cy * cx;
    return R;
}

// straight-line (no vote, no branches) euler extraction of M = R1 .* pp
__device__ __forceinline__ void rot_euler(const M7& R1, const M7& pp,
                                          float& e0, float& e1, float& e2) {
    float M00 = R1.m0 * pp.m0;
    float M10 = R1.m3 * pp.m3;
    float M20 = R1.m6 * pp.m6;
    float M21 = R1.m7 * pp.m7;
    float M22 = R1.m8 * pp.m8;
    float M11 = R1.m4 * pp.m4;
    float M12 = R1.m5 * pp.m5;
    float s   = fmaf(M00, M00, M10 * M10);
    float sy  = sqrtf(s);
    bool sing = sy < 1e-6f;
    float e0n = fast_atan2f(M21, M22);
    float e0s = fast_atan2f(-M12, M11);
    float e2n = fast_atan2f(M10, M00);
    e0 = sing ? e0s : e0n;
    e1 = fast_atan2_posx(-M20, sy);
    e2 = sing ? 0.0f : e2n;
}

__global__ void __launch_bounds__(TPB, 7)
cycle_loss_kernel(const float* __restrict__ pred, const float* __restrict__ gt,
                  float* __restrict__ out, double scale)
{
    __shared__ float s[TPB * STR];     // slot 2r = pred row r, slot 2r+1 = gt row r
    const int tid = threadIdx.x;

    // ---- coalesced float4 stage into smem (odd stride 61) ----
    {
        long base = (long)blockIdx.x * ROWS_B * ROWF;
        const float4* p4 = (const float4*)(pred + base);
        const float4* g4 = (const float4*)(gt + base);
        #pragma unroll
        for (int j = tid; j < ROWS_B * (ROWF / 4); j += TPB) {
            int r = j / 15;
            int c = (j % 15) * 4;
            float4 v = p4[j];
            float* d = &s[(2 * r) * STR + c];
            d[0] = v.x; d[1] = v.y; d[2] = v.z; d[3] = v.w;
            float4 w = g4[j];
            float* d2 = &s[(2 * r + 1) * STR + c];
            d2[0] = w.x; d2[1] = w.y; d2[2] = w.z; d2[3] = w.w;
        }
    }
    __syncthreads();

    // this thread owns one signal of one row (pairs share a warp: lanes 2k/2k+1)
    const float* P = &s[tid * STR];

    float acc = 0.0f;   // both lanes of a pair accumulate identical d^2; halved at end

    // ---------------- translation part ----------------
    {
        float v0 = P[0], v1 = P[1], v2 = P[2];
        {
            float d0 = v0 - __shfl_xor_sync(0xffffffffu, v0, 1);
            float d1 = v1 - __shfl_xor_sync(0xffffffffu, v1, 1);
            float d2 = v2 - __shfl_xor_sync(0xffffffffu, v2, 1);
            acc += d0 * d0 + d1 * d1 + d2 * d2;
        }
        float c0 = 0.f, c1 = 0.f, c2 = 0.f;
        #pragma unroll
        for (int i = 1; i < NSTEP; i++) {
            v0 = 2.0f * v0 + c0;
            v1 = 2.0f * v1 + c1;
            v2 = 2.0f * v2 + c2;
            float d0 = v0 - __shfl_xor_sync(0xffffffffu, v0, 1);
            float d1 = v1 - __shfl_xor_sync(0xffffffffu, v1, 1);
            float d2 = v2 - __shfl_xor_sync(0xffffffffu, v2, 1);
            acc += d0 * d0 + d1 * d1 + d2 * d2;
            const float* tp = &P[i * 6];
            c0 += tp[0]; c1 += tp[1]; c2 += tp[2];
        }
    }

    // ---------------- rotation part ----------------
    {
        M7 R1 = euler_to_mat7(P[9], P[10], P[11]);
        M7 pp = {1.f, 1.f, 1.f, 1.f, 1.f, 1.f, 1.f};

        for (int i = 0; i < NSTEP; i++) {
            float e0, e1, e2;
            rot_euler(R1, pp, e0, e1, e2);
            float d0 = e0 - __shfl_xor_sync(0xffffffffu, e0, 1);
            float d1 = e1 - __shfl_xor_sync(0xffffffffu, e1, 1);
            float d2 = e2 - __shfl_xor_sync(0xffffffffu, e2, 1);
            acc += d0 * d0 + d1 * d1 + d2 * d2;

            if (i < NSTEP - 1) {            // last update unused
                M7 R = euler_to_mat7(P[i * 6 + 3], P[i * 6 + 4], P[i * 6 + 5]);
                pp.m0 *= R.m0; pp.m3 *= R.m3; pp.m4 *= R.m4; pp.m5 *= R.m5;
                pp.m6 *= R.m6; pp.m7 *= R.m7; pp.m8 *= R.m8;
            }
        }
    }

    // ---------------- block reduction ----------------
    #pragma unroll
    for (int o = 16; o > 0; o >>= 1)
        acc += __shfl_down_sync(0xffffffffu, acc, o);

    __shared__ float wsum[TPB / 32];
    if ((tid & 31) == 0) wsum[tid >> 5] = acc;
    __syncthreads();

    __shared__ bool is_last;
    if (tid == 0) {
        float sblk = 0.0f;
        #pragma unroll
        for (int w = 0; w < TPB / 32; w++) sblk += wsum[w];
        g_partials[blockIdx.x] = sblk;
        __threadfence();
        unsigned int c = atomicAdd(&g_count, 1u);
        is_last = (c == gridDim.x - 1);
    }
    __syncthreads();

    // ---------------- last block: deterministic final reduce ----------------
    if (is_last) {
        double sd = 0.0;
        for (int i = tid; i < (int)gridDim.x; i += TPB)
            sd += (double)g_partials[i];
        #pragma unroll
        for (int o = 16; o > 0; o >>= 1)
            sd += __shfl_down_sync(0xffffffffu, sd, o);
        __shared__ double dsum[TPB / 32];
        if ((tid & 31) == 0) dsum[tid >> 5] = sd;
        __syncthreads();
        if (tid == 0) {
            double t = 0.0;
            #pragma unroll
            for (int w = 0; w < TPB / 32; w++) t += dsum[w];
            out[0] = (float)(t * scale);
            g_count = 0;            // reset for next graph replay
        }
    }
}

extern "C" void kernel_launch(void* const* d_in, const int* in_sizes, int n_in,
                              void* d_out, int out_size)
{
    const float* pred = (const float*)d_in[0];
    const float* gt   = (const float*)d_in[1];
    int batch   = in_sizes[0] / ROWF;       // 262144
    int nblocks = batch / ROWS_B;           // 4096

    // loss = sum / (60 * B * B); extra 0.5 because both lanes of a pair
    // accumulate the same squared difference.
    double scale = 0.5 / (60.0 * (double)batch * (double)batch);
    cycle_loss_kernel<<<nblocks, TPB>>>(pred, gt, (float*)d_out, scale);
}